// round 11
// baseline (speedup 1.0000x reference)
#include <cuda_runtime.h>
#include <math_constants.h>
#include <cstdint>

// Problem shape (fixed)
#define Bdim 2048
#define Ddim 25088
#define Cdim 100
#define CPAD 128

#define KT 128                  // fp16 K per iteration
#define NKT (Ddim / KT)         // 196 total k-tiles
#define BM 128
#define MAXS 10                 // max k-splits per m-tile

// smem tile geometry: 128 rows x 128 fp16 (256 B), row stride padded to 272 B
#define STR 272
#define TILE_SZ (128 * STR)              // 34816 B
#define BUF_SZ (2 * TILE_SZ)             // A, B
#define SMEM_TOTAL (2 * BUF_SZ)          // 139264 B

#define W32 12544                        // u32 per W row (25088 fp16)

// ---------------- scratch ----------------
__device__ float    g_part[(size_t)MAXS * Bdim * CPAD];   // split partials
__device__ float    g_nfsq[MAXS * 4 * Bdim];              // feature norm^2 partials
__device__ uint32_t g_wh[(size_t)CPAD * W32];             // raw W, fp16 (rows>=100 stay 0)
__device__ float    g_wnsq_p[Cdim * 8];                   // weight norm^2 partials
__device__ unsigned long long g_loss_fx;                  // fixed-point loss sum (2^-32)
__device__ int      g_corr_acc;
__device__ int      g_vld_acc;
__device__ unsigned g_ticket;

// ---------------- helpers ----------------
__device__ __forceinline__ uint32_t smem_u32(const void* p) {
    uint32_t a;
    asm("{ .reg .u64 t; cvta.to.shared.u64 t, %1; cvt.u32.u64 %0, t; }" : "=r"(a) : "l"(p));
    return a;
}
__device__ __forceinline__ void ldsm4(uint32_t addr, uint32_t& r0, uint32_t& r1,
                                      uint32_t& r2, uint32_t& r3) {
    asm volatile("ldmatrix.sync.aligned.m8n8.x4.shared.b16 {%0,%1,%2,%3}, [%4];"
                 : "=r"(r0), "=r"(r1), "=r"(r2), "=r"(r3) : "r"(addr));
}
__device__ __forceinline__ void mma_f16(float& d0, float& d1, float& d2, float& d3,
                                        uint32_t a0, uint32_t a1, uint32_t a2, uint32_t a3,
                                        uint32_t b0, uint32_t b1) {
    asm volatile("mma.sync.aligned.m16n8k16.row.col.f32.f16.f16.f32 "
                 "{%0,%1,%2,%3}, {%4,%5,%6,%7}, {%8,%9}, {%0,%1,%2,%3};"
                 : "+f"(d0), "+f"(d1), "+f"(d2), "+f"(d3)
                 : "r"(a0), "r"(a1), "r"(a2), "r"(a3), "r"(b0), "r"(b1));
}
__device__ __forceinline__ uint32_t cvt_f16x2(float x, float y) {
    uint32_t r;
    asm("cvt.rn.f16x2.f32 %0, %1, %2;" : "=r"(r) : "f"(y), "f"(x));
    return r;
}
#define CP16(dst, src) asm volatile("cp.async.cg.shared.global [%0], [%1], 16;" :: "r"(dst), "l"(src))
#define CP_COMMIT()    asm volatile("cp.async.commit_group;" ::: "memory")
#define CP_WAIT1()     asm volatile("cp.async.wait_group 1;" ::: "memory")
#define CP_WAIT0()     asm volatile("cp.async.wait_group 0;" ::: "memory")

// ======================= W prep: grid (100, 8), partial norms ==================
// Each block converts 3136 floats of one row and writes one norm^2 partial.
__global__ __launch_bounds__(256) void prep_w_kernel(const float* __restrict__ W) {
    const int row = blockIdx.x;                // 0..99
    const int ch  = blockIdx.y;                // 0..7
    const int t   = threadIdx.x;
    __shared__ float red[256];

    if (row == 0 && ch == 0 && t == 0) {
        g_loss_fx = 0ull; g_corr_acc = 0; g_vld_acc = 0; g_ticket = 0u;
    }

    const float4* r4 = (const float4*)(W + (size_t)row * Ddim + ch * 3136);
    uint2* dh = (uint2*)(g_wh + (size_t)row * W32 + ch * 1568);
    float s = 0.f;
    for (int i = t; i < 784; i += 256) {
        float4 v = r4[i];
        s += v.x * v.x + v.y * v.y + v.z * v.z + v.w * v.w;
        dh[i] = make_uint2(cvt_f16x2(v.x, v.y), cvt_f16x2(v.z, v.w));
    }
    red[t] = s;
    __syncthreads();
    for (int off = 128; off > 0; off >>= 1) {
        if (t < off) red[t] += red[t + off];
        __syncthreads();
    }
    if (t == 0) g_wnsq_p[row * 8 + ch] = red[0];
}

// ======================= HMMA fp16 GEMM (148 CTAs, KT=128) =====================
// grid 148, 512 threads. Warps: wm = w&3 (SMSP), wn = w>>2; wn==3 -> 1 n8 group.
__global__ void __launch_bounds__(512, 1)
gemm_mma_kernel(const float* __restrict__ F) {
    extern __shared__ char smem[];
    const uint32_t sbase = smem_u32(smem);

    // block -> (m-tile, split)
    const int bid = blockIdx.x;
    int mt, s, S;
    if (bid < 108) { mt = bid / 9;  s = bid - mt * 9;          S = 9; }
    else           { int b2 = bid - 108; mt = 12 + b2 / 10; s = b2 % 10; S = 10; }
    const int base = NKT / S, rem = NKT % S;
    const int nt   = base + (s < rem ? 1 : 0);
    const int kt0  = s * base + (s < rem ? s : rem);
    const int m0   = mt * BM;
    const int k0   = kt0 * KT;

    const int t    = threadIdx.x;
    const int lane = t & 31;
    const int w    = t >> 5;

    // ---- loader mapping: row = t/4, q = t&3 covers 32 floats (64 B fp16) ----
    const int row = t >> 2;
    const int q   = t & 3;

    const float4* gA = (const float4*)(F + (size_t)(m0 + row) * Ddim + k0) + q * 8;
    const uint32_t stsA_off = row * STR + q * 64;
    const char* srcB = (const char*)g_wh + (size_t)row * (W32 * 4) + (size_t)k0 * 2 + q * 64;
    const uint32_t dstB_off = TILE_SZ + row * STR + q * 64;

    // ---- MMA mapping ----
    const int wm = w & 3;
    const int wn = w >> 2;
    const int nmax = (wn == 3) ? 1 : 4;
    const uint32_t aAddr0 = sbase + (wm * 32 + (lane & 15)) * STR + (lane >> 4) * 16;
    const uint32_t bAddr0 = sbase + TILE_SZ +
        (wn * 32 + (lane & 7) + (lane >> 4) * 8) * STR + ((lane >> 3) & 1) * 16;

    float acc[2][4][4];
#pragma unroll
    for (int i = 0; i < 2; i++)
#pragma unroll
        for (int j = 0; j < 4; j++)
#pragma unroll
            for (int e = 0; e < 4; e++) acc[i][j][e] = 0.f;

    float nf = 0.f;
    float4 ra[8];

    // prologue: A tile 0 into regs; B tile 0 cp.async into buf0
#pragma unroll
    for (int j = 0; j < 8; j++) ra[j] = gA[j];
#pragma unroll
    for (int c = 0; c < 4; c++) CP16(sbase + dstB_off + c * 16, srcB + c * 16);
    CP_COMMIT();

    for (int it = 0; it < nt; it++) {
        const uint32_t bufo = (it & 1) ? BUF_SZ : 0;
        const uint32_t nbuf = (it & 1) ? 0 : BUF_SZ;

        // convert tile `it` BEFORE the barrier (overlaps other warps' MMA tail)
        uint32_t pk[16];
#pragma unroll
        for (int j = 0; j < 8; j++) {
            float4 v = ra[j];
            nf += v.x * v.x + v.y * v.y + v.z * v.z + v.w * v.w;
            pk[2 * j]     = cvt_f16x2(v.x, v.y);
            pk[2 * j + 1] = cvt_f16x2(v.z, v.w);
        }

        __syncthreads();   // buf writable (prior MMA reads done)

        // issue B(it+1) into other buffer
        if (it + 1 < nt) {
            const char* sB = srcB + (size_t)(it + 1) * 256;
#pragma unroll
            for (int c = 0; c < 4; c++) CP16(sbase + nbuf + dstB_off + c * 16, sB + c * 16);
            CP_COMMIT();
        }

        // store A tile `it` (4 STS.128)
#pragma unroll
        for (int c = 0; c < 4; c++)
            *(uint4*)(smem + bufo + stsA_off + c * 16) =
                make_uint4(pk[4 * c], pk[4 * c + 1], pk[4 * c + 2], pk[4 * c + 3]);

        // A prefetch for it+1 (covered by the MMA phase)
        if (it + 1 < nt) {
#pragma unroll
            for (int j = 0; j < 8; j++) ra[j] = gA[(it + 1) * 32 + j];
        }

        if (it + 1 < nt) { CP_WAIT1(); } else { CP_WAIT0(); }
        __syncthreads();   // tile `it` fully visible

        // MMA: 8 k16 steps
#pragma unroll
        for (int ks = 0; ks < 8; ks++) {
            uint32_t ah[2][4], bh[2][4];
#pragma unroll
            for (int mi = 0; mi < 2; mi++) {
                const uint32_t a = aAddr0 + bufo + mi * 16 * STR + ks * 32;
                ldsm4(a, ah[mi][0], ah[mi][1], ah[mi][2], ah[mi][3]);
            }
            {
                const uint32_t b = bAddr0 + bufo + ks * 32;
                ldsm4(b, bh[0][0], bh[0][1], bh[0][2], bh[0][3]);
                if (nmax == 4)
                    ldsm4(b + 16 * STR, bh[1][0], bh[1][1], bh[1][2], bh[1][3]);
            }
#pragma unroll
            for (int mi = 0; mi < 2; mi++)
#pragma unroll
                for (int nj = 0; nj < 4; nj++) {
                    if (nj >= nmax) break;
                    float* d = acc[mi][nj];
                    mma_f16(d[0], d[1], d[2], d[3],
                            ah[mi][0], ah[mi][1], ah[mi][2], ah[mi][3],
                            bh[nj >> 1][2 * (nj & 1)], bh[nj >> 1][2 * (nj & 1) + 1]);
                }
        }
    }

    // feature norm^2 partial (slot s, quarter q)
    g_nfsq[(s * 4 + q) * Bdim + (m0 + row)] = nf;

    // write live partials into split slot s
#pragma unroll
    for (int mi = 0; mi < 2; mi++)
#pragma unroll
        for (int nj = 0; nj < 4; nj++) {
            if (nj >= nmax) break;
#pragma unroll
            for (int e = 0; e < 4; e++) {
                const int r = m0 + wm * 32 + mi * 16 + (lane >> 2) + (e >> 1) * 8;
                const int c = wn * 32 + nj * 8 + (lane & 3) * 2 + (e & 1);
                g_part[((size_t)s * Bdim + r) * CPAD + c] = acc[mi][nj][e];
            }
        }
}

// ======================= warp-per-row epilogue + fused finalize ==================
// grid 256 blocks x 256 threads; warp w handles row = bid*8 + w.
__global__ __launch_bounds__(256) void epilogue_kernel(const void* __restrict__ labels,
                                                       float* __restrict__ out,
                                                       int out_size) {
    const int t    = threadIdx.x;
    const int lane = t & 31;
    const int row  = blockIdx.x * 8 + (t >> 5);

    __shared__ float s_wninv[CPAD];
    if (t < CPAD) {
        float ws = 0.f;
        if (t < Cdim) {
#pragma unroll
            for (int i = 0; i < 8; i++) ws += g_wnsq_p[t * 8 + i];
        }
        s_wninv[t] = 1.0f / fmaxf(sqrtf(ws), 1e-8f);
    }
    __syncthreads();

    // int64-vs-int32 label layout sniff (per warp; global property)
    const int hiw = ((const int*)labels)[2 * lane + 1];
    const unsigned bal = __ballot_sync(0xFFFFFFFFu, (hiw == 0) || (hiw == -1));
    const int is64 = (bal == 0xFFFFFFFFu);

    const int mt = row >> 7;
    const int S  = (mt < 12) ? 9 : 10;
    const int n4 = 4 * S;

    // feature norm
    float nf = (lane < n4) ? g_nfsq[lane * Bdim + row] : 0.f;
    if (lane < n4 - 32) nf += g_nfsq[(32 + lane) * Bdim + row];
#pragma unroll
    for (int o = 16; o > 0; o >>= 1) nf += __shfl_xor_sync(0xFFFFFFFFu, nf, o);
    const float fninv = 10.0f / fmaxf(sqrtf(nf), 1e-8f);

    // logits (4 per lane: cols lane+32j)
    float lg[4];
#pragma unroll
    for (int j = 0; j < 4; j++) {
        const int c = lane + 32 * j;
        if (c < Cdim) {
            float g = 0.f;
            for (int s2 = 0; s2 < S; s2++)
                g += g_part[((size_t)s2 * Bdim + row) * CPAD + c];
            lg[j] = g * fninv * s_wninv[c];
        } else {
            lg[j] = -CUDART_INF_F;
        }
    }

    // max + first-index argmax
    float mv = lg[0]; int mi = lane;
#pragma unroll
    for (int j = 1; j < 4; j++)
        if (lg[j] > mv) { mv = lg[j]; mi = lane + 32 * j; }
#pragma unroll
    for (int o = 16; o > 0; o >>= 1) {
        const float ov = __shfl_xor_sync(0xFFFFFFFFu, mv, o);
        const int   oi = __shfl_xor_sync(0xFFFFFFFFu, mi, o);
        if (ov > mv || (ov == mv && oi < mi)) { mv = ov; mi = oi; }
    }

    // log-sum-exp
    float es = 0.f;
#pragma unroll
    for (int j = 0; j < 4; j++)
        if (lane + 32 * j < Cdim) es += expf(lg[j] - mv);
#pragma unroll
    for (int o = 16; o > 0; o >>= 1) es += __shfl_xor_sync(0xFFFFFFFFu, es, o);
    const float lse = logf(es) + mv;

    // label (lane 0 loads, broadcast)
    int labi0 = 0;
    if (lane == 0) {
        long long lab = is64 ? ((const long long*)labels)[row]
                             : (long long)((const int*)labels)[row];
        labi0 = (int)lab;
    }
    const int labi = __shfl_sync(0xFFFFFFFFu, labi0, 0);

    if (labi >= 0) {
        const int sl = labi & 31, jj = labi >> 5;
        const float cand = (jj == 0) ? lg[0] : (jj == 1) ? lg[1] : (jj == 2) ? lg[2] : lg[3];
        const float lv = __shfl_sync(0xFFFFFFFFu, cand, sl);
        if (lane == 0) {
            const float nll = lse - lv;
            const unsigned long long fx =
                (unsigned long long)(fmax((double)nll, 0.0) * 4294967296.0 + 0.5);
            atomicAdd(&g_loss_fx, fx);
            if (mi == labi) atomicAdd(&g_corr_acc, 1);
            atomicAdd(&g_vld_acc, 1);
        }
    }

    if (lane == 0) {
        __threadfence();
        const unsigned tk = atomicAdd(&g_ticket, 1u);
        if (tk == (unsigned)(Bdim - 1)) {
            const unsigned long long ls = atomicAdd(&g_loss_fx, 0ull);
            const int cr = atomicAdd(&g_corr_acc, 0);
            const int vl = atomicAdd(&g_vld_acc, 0);
            const double loss_sum = (double)ls * (1.0 / 4294967296.0);
            const float nv = (float)vl;
            out[0] = (float)(loss_sum / (double)fmaxf(nv, 1.0f));
            if (out_size > 1) out[1] = (float)cr / (nv + 1e-10f);
        }
    }
}

// ======================= launch =======================
extern "C" void kernel_launch(void* const* d_in, const int* in_sizes, int n_in,
                              void* d_out, int out_size) {
    int fi = 0, li = 0;
    for (int i = 1; i < n_in; i++) {
        if (in_sizes[i] > in_sizes[fi]) fi = i;
        if (in_sizes[i] < in_sizes[li]) li = i;
    }
    int wi = 0;
    for (int i = 0; i < n_in; i++) if (i != fi && i != li) wi = i;

    const float* F = (const float*)d_in[fi];
    const float* W = (const float*)d_in[wi];
    const void*  L = d_in[li];

    cudaFuncSetAttribute(gemm_mma_kernel,
                         cudaFuncAttributeMaxDynamicSharedMemorySize, SMEM_TOTAL);

    prep_w_kernel<<<dim3(Cdim, 8), 256>>>(W);
    gemm_mma_kernel<<<148, 512, SMEM_TOTAL>>>(F);
    epilogue_kernel<<<Bdim / 8, 256>>>(L, (float*)d_out, out_size);
}

// round 12
// speedup vs baseline: 1.5653x; 1.5653x over previous
#include <cuda_runtime.h>
#include <math_constants.h>
#include <cstdint>

// Problem shape (fixed)
#define Bdim 2048
#define Ddim 25088
#define Cdim 100
#define CPAD 128

#define KT 64                   // fp16 K per iteration
#define NKT (Ddim / KT)         // 392 total k-tiles
#define BM 128
#define MAXS 10                 // max k-splits per m-tile

// smem tile geometry: 128 rows x 64 fp16 (128 B), row stride padded to 144 B
#define STR 144
#define TILE_SZ (128 * STR)              // 18432 B
#define BUF_SZ (2 * TILE_SZ)             // A, B
#define SMEM_TOTAL (2 * BUF_SZ)          // 73728 B

#define W32 12544                        // u32 per W row (25088 fp16)

// ---------------- scratch ----------------
__device__ float    g_part[(size_t)MAXS * Bdim * CPAD];   // split partials
__device__ float    g_nfsq[MAXS * 4 * Bdim];              // feature norm^2 partials
__device__ uint32_t g_wh[(size_t)CPAD * W32];             // raw W, fp16 (rows>=100 stay 0)
__device__ float    g_wnsq_p[Cdim * 8];                   // weight norm^2 partials
__device__ unsigned long long g_loss_fx;                  // fixed-point loss sum (2^-32)
__device__ int      g_corr_acc;
__device__ int      g_vld_acc;
__device__ unsigned g_ticket;

// ---------------- helpers ----------------
__device__ __forceinline__ uint32_t smem_u32(const void* p) {
    uint32_t a;
    asm("{ .reg .u64 t; cvta.to.shared.u64 t, %1; cvt.u32.u64 %0, t; }" : "=r"(a) : "l"(p));
    return a;
}
__device__ __forceinline__ void ldsm4(uint32_t addr, uint32_t& r0, uint32_t& r1,
                                      uint32_t& r2, uint32_t& r3) {
    asm volatile("ldmatrix.sync.aligned.m8n8.x4.shared.b16 {%0,%1,%2,%3}, [%4];"
                 : "=r"(r0), "=r"(r1), "=r"(r2), "=r"(r3) : "r"(addr));
}
__device__ __forceinline__ void mma_f16(float& d0, float& d1, float& d2, float& d3,
                                        uint32_t a0, uint32_t a1, uint32_t a2, uint32_t a3,
                                        uint32_t b0, uint32_t b1) {
    asm volatile("mma.sync.aligned.m16n8k16.row.col.f32.f16.f16.f32 "
                 "{%0,%1,%2,%3}, {%4,%5,%6,%7}, {%8,%9}, {%0,%1,%2,%3};"
                 : "+f"(d0), "+f"(d1), "+f"(d2), "+f"(d3)
                 : "r"(a0), "r"(a1), "r"(a2), "r"(a3), "r"(b0), "r"(b1));
}
__device__ __forceinline__ uint32_t cvt_f16x2(float x, float y) {
    uint32_t r;
    asm("cvt.rn.f16x2.f32 %0, %1, %2;" : "=r"(r) : "f"(y), "f"(x));
    return r;
}
#define CP16(dst, src) asm volatile("cp.async.cg.shared.global [%0], [%1], 16;" :: "r"(dst), "l"(src))
#define CP_COMMIT()    asm volatile("cp.async.commit_group;" ::: "memory")
#define CP_WAIT1()     asm volatile("cp.async.wait_group 1;" ::: "memory")
#define CP_WAIT0()     asm volatile("cp.async.wait_group 0;" ::: "memory")

// ======================= W prep: grid (100, 8), partial norms ==================
__global__ __launch_bounds__(256) void prep_w_kernel(const float* __restrict__ W) {
    const int row = blockIdx.x;                // 0..99
    const int ch  = blockIdx.y;                // 0..7
    const int t   = threadIdx.x;
    __shared__ float red[256];

    if (row == 0 && ch == 0 && t == 0) {
        g_loss_fx = 0ull; g_corr_acc = 0; g_vld_acc = 0; g_ticket = 0u;
    }

    const float4* r4 = (const float4*)(W + (size_t)row * Ddim + ch * 3136);
    uint2* dh = (uint2*)(g_wh + (size_t)row * W32 + ch * 1568);
    float s = 0.f;
    for (int i = t; i < 784; i += 256) {
        float4 v = r4[i];
        s += v.x * v.x + v.y * v.y + v.z * v.z + v.w * v.w;
        dh[i] = make_uint2(cvt_f16x2(v.x, v.y), cvt_f16x2(v.z, v.w));
    }
    red[t] = s;
    __syncthreads();
    for (int off = 128; off > 0; off >>= 1) {
        if (t < off) red[t] += red[t + off];
        __syncthreads();
    }
    if (t == 0) g_wnsq_p[row * 8 + ch] = red[0];
}

// ======================= HMMA fp16 GEMM (148 CTAs, KT=64) ======================
// grid 148, 512 threads. Warps: wm = w&3 (SMSP), wn = w>>2; wn==3 -> 1 n8 group.
__global__ void __launch_bounds__(512, 1)
gemm_mma_kernel(const float* __restrict__ F) {
    extern __shared__ char smem[];
    const uint32_t sbase = smem_u32(smem);

    // block -> (m-tile, split)
    const int bid = blockIdx.x;
    int mt, s, S;
    if (bid < 108) { mt = bid / 9;  s = bid - mt * 9;          S = 9; }
    else           { int b2 = bid - 108; mt = 12 + b2 / 10; s = b2 % 10; S = 10; }
    const int base = NKT / S, rem = NKT % S;
    const int nt   = base + (s < rem ? 1 : 0);
    const int kt0  = s * base + (s < rem ? s : rem);
    const int m0   = mt * BM;
    const int k0   = kt0 * KT;

    const int t    = threadIdx.x;
    const int lane = t & 31;
    const int w    = t >> 5;

    // ---- loader mapping: row = t/4, q = t&3 covers 16 floats (32 B fp16) ----
    const int row = t >> 2;
    const int q   = t & 3;

    const float4* gA = (const float4*)(F + (size_t)(m0 + row) * Ddim + k0) + q * 4;
    const uint32_t stsA_off = row * STR + q * 32;
    const char* srcB = (const char*)g_wh + (size_t)row * (W32 * 4) + (size_t)k0 * 2 + q * 32;
    const uint32_t dstB_off = TILE_SZ + row * STR + q * 32;

    // ---- MMA mapping ----
    const int wm = w & 3;
    const int wn = w >> 2;
    const int nmax = (wn == 3) ? 1 : 4;
    const uint32_t aAddr0 = sbase + (wm * 32 + (lane & 15)) * STR + (lane >> 4) * 16;
    const uint32_t bAddr0 = sbase + TILE_SZ +
        (wn * 32 + (lane & 7) + (lane >> 4) * 8) * STR + ((lane >> 3) & 1) * 16;

    float acc[2][4][4];
#pragma unroll
    for (int i = 0; i < 2; i++)
#pragma unroll
        for (int j = 0; j < 4; j++)
#pragma unroll
            for (int e = 0; e < 4; e++) acc[i][j][e] = 0.f;

    float nf = 0.f;
    float4 ra[4];

    // prologue: A tile 0 into regs; B tile 0 cp.async into buf0
#pragma unroll
    for (int j = 0; j < 4; j++) ra[j] = gA[j];
    CP16(sbase + dstB_off, srcB);
    CP16(sbase + dstB_off + 16, srcB + 16);
    CP_COMMIT();

    for (int it = 0; it < nt; it++) {
        const uint32_t bufo = (it & 1) ? BUF_SZ : 0;
        const uint32_t nbuf = (it & 1) ? 0 : BUF_SZ;

        // convert tile `it` BEFORE the barrier (overlaps other warps' MMA tail)
        uint32_t pk[8];
#pragma unroll
        for (int j = 0; j < 4; j++) {
            float4 v = ra[j];
            nf += v.x * v.x + v.y * v.y + v.z * v.z + v.w * v.w;
            pk[2 * j]     = cvt_f16x2(v.x, v.y);
            pk[2 * j + 1] = cvt_f16x2(v.z, v.w);
        }

        __syncthreads();   // buf writable (prior MMA reads done)

        // issue B(it+1) into other buffer
        if (it + 1 < nt) {
            const char* sB = srcB + (size_t)(it + 1) * 128;
            CP16(sbase + nbuf + dstB_off, sB);
            CP16(sbase + nbuf + dstB_off + 16, sB + 16);
            CP_COMMIT();
        }

        // store A tile `it` (2 STS.128)
        *(uint4*)(smem + bufo + stsA_off)      = make_uint4(pk[0], pk[1], pk[2], pk[3]);
        *(uint4*)(smem + bufo + stsA_off + 16) = make_uint4(pk[4], pk[5], pk[6], pk[7]);

        // single-stage A prefetch (covered by the MMA phase)
        if (it + 1 < nt) {
#pragma unroll
            for (int j = 0; j < 4; j++) ra[j] = gA[(it + 1) * 16 + j];
        }

        if (it + 1 < nt) { CP_WAIT1(); } else { CP_WAIT0(); }
        __syncthreads();   // tile `it` fully visible

        // MMA: 4 k16 steps
#pragma unroll
        for (int ks = 0; ks < 4; ks++) {
            uint32_t ah[2][4], bh[2][4];
#pragma unroll
            for (int mi = 0; mi < 2; mi++) {
                const uint32_t a = aAddr0 + bufo + mi * 16 * STR + ks * 32;
                ldsm4(a, ah[mi][0], ah[mi][1], ah[mi][2], ah[mi][3]);
            }
            {
                const uint32_t b = bAddr0 + bufo + ks * 32;
                ldsm4(b, bh[0][0], bh[0][1], bh[0][2], bh[0][3]);
                if (nmax == 4)
                    ldsm4(b + 16 * STR, bh[1][0], bh[1][1], bh[1][2], bh[1][3]);
            }
#pragma unroll
            for (int mi = 0; mi < 2; mi++)
#pragma unroll
                for (int nj = 0; nj < 4; nj++) {
                    if (nj >= nmax) break;
                    float* d = acc[mi][nj];
                    mma_f16(d[0], d[1], d[2], d[3],
                            ah[mi][0], ah[mi][1], ah[mi][2], ah[mi][3],
                            bh[nj >> 1][2 * (nj & 1)], bh[nj >> 1][2 * (nj & 1) + 1]);
                }
        }
    }

    // feature norm^2 partial (slot s, quarter q)
    g_nfsq[(s * 4 + q) * Bdim + (m0 + row)] = nf;

    // write live partials into split slot s
#pragma unroll
    for (int mi = 0; mi < 2; mi++)
#pragma unroll
        for (int nj = 0; nj < 4; nj++) {
            if (nj >= nmax) break;
#pragma unroll
            for (int e = 0; e < 4; e++) {
                const int r = m0 + wm * 32 + mi * 16 + (lane >> 2) + (e >> 1) * 8;
                const int c = wn * 32 + nj * 8 + (lane & 3) * 2 + (e & 1);
                g_part[((size_t)s * Bdim + r) * CPAD + c] = acc[mi][nj][e];
            }
        }
}

// ======================= warp-per-row epilogue + fused finalize ==================
// grid 256 blocks x 256 threads; warp w handles row = bid*8 + w.
__global__ __launch_bounds__(256) void epilogue_kernel(const void* __restrict__ labels,
                                                       float* __restrict__ out,
                                                       int out_size) {
    const int t    = threadIdx.x;
    const int lane = t & 31;
    const int row  = blockIdx.x * 8 + (t >> 5);

    __shared__ float s_wninv[CPAD];
    if (t < CPAD) {
        float ws = 0.f;
        if (t < Cdim) {
#pragma unroll
            for (int i = 0; i < 8; i++) ws += g_wnsq_p[t * 8 + i];
        }
        s_wninv[t] = 1.0f / fmaxf(sqrtf(ws), 1e-8f);
    }
    __syncthreads();

    // int64-vs-int32 label layout sniff (per warp; global property)
    const int hiw = ((const int*)labels)[2 * lane + 1];
    const unsigned bal = __ballot_sync(0xFFFFFFFFu, (hiw == 0) || (hiw == -1));
    const int is64 = (bal == 0xFFFFFFFFu);

    const int mt = row >> 7;
    const int S  = (mt < 12) ? 9 : 10;
    const int n4 = 4 * S;

    // feature norm
    float nf = (lane < n4) ? g_nfsq[lane * Bdim + row] : 0.f;
    if (lane < n4 - 32) nf += g_nfsq[(32 + lane) * Bdim + row];
#pragma unroll
    for (int o = 16; o > 0; o >>= 1) nf += __shfl_xor_sync(0xFFFFFFFFu, nf, o);
    const float fninv = 10.0f / fmaxf(sqrtf(nf), 1e-8f);

    // logits (4 per lane: cols lane+32j)
    float lg[4];
#pragma unroll
    for (int j = 0; j < 4; j++) {
        const int c = lane + 32 * j;
        if (c < Cdim) {
            float g = 0.f;
            for (int s2 = 0; s2 < S; s2++)
                g += g_part[((size_t)s2 * Bdim + row) * CPAD + c];
            lg[j] = g * fninv * s_wninv[c];
        } else {
            lg[j] = -CUDART_INF_F;
        }
    }

    // max + first-index argmax
    float mv = lg[0]; int mi = lane;
#pragma unroll
    for (int j = 1; j < 4; j++)
        if (lg[j] > mv) { mv = lg[j]; mi = lane + 32 * j; }
#pragma unroll
    for (int o = 16; o > 0; o >>= 1) {
        const float ov = __shfl_xor_sync(0xFFFFFFFFu, mv, o);
        const int   oi = __shfl_xor_sync(0xFFFFFFFFu, mi, o);
        if (ov > mv || (ov == mv && oi < mi)) { mv = ov; mi = oi; }
    }

    // log-sum-exp
    float es = 0.f;
#pragma unroll
    for (int j = 0; j < 4; j++)
        if (lane + 32 * j < Cdim) es += expf(lg[j] - mv);
#pragma unroll
    for (int o = 16; o > 0; o >>= 1) es += __shfl_xor_sync(0xFFFFFFFFu, es, o);
    const float lse = logf(es) + mv;

    // label (lane 0 loads, broadcast)
    int labi0 = 0;
    if (lane == 0) {
        long long lab = is64 ? ((const long long*)labels)[row]
                             : (long long)((const int*)labels)[row];
        labi0 = (int)lab;
    }
    const int labi = __shfl_sync(0xFFFFFFFFu, labi0, 0);

    if (labi >= 0) {
        const int sl = labi & 31, jj = labi >> 5;
        const float cand = (jj == 0) ? lg[0] : (jj == 1) ? lg[1] : (jj == 2) ? lg[2] : lg[3];
        const float lv = __shfl_sync(0xFFFFFFFFu, cand, sl);
        if (lane == 0) {
            const float nll = lse - lv;
            const unsigned long long fx =
                (unsigned long long)(fmax((double)nll, 0.0) * 4294967296.0 + 0.5);
            atomicAdd(&g_loss_fx, fx);
            if (mi == labi) atomicAdd(&g_corr_acc, 1);
            atomicAdd(&g_vld_acc, 1);
        }
    }

    if (lane == 0) {
        __threadfence();
        const unsigned tk = atomicAdd(&g_ticket, 1u);
        if (tk == (unsigned)(Bdim - 1)) {
            const unsigned long long ls = atomicAdd(&g_loss_fx, 0ull);
            const int cr = atomicAdd(&g_corr_acc, 0);
            const int vl = atomicAdd(&g_vld_acc, 0);
            const double loss_sum = (double)ls * (1.0 / 4294967296.0);
            const float nv = (float)vl;
            out[0] = (float)(loss_sum / (double)fmaxf(nv, 1.0f));
            if (out_size > 1) out[1] = (float)cr / (nv + 1e-10f);
        }
    }
}

// ======================= launch =======================
extern "C" void kernel_launch(void* const* d_in, const int* in_sizes, int n_in,
                              void* d_out, int out_size) {
    int fi = 0, li = 0;
    for (int i = 1; i < n_in; i++) {
        if (in_sizes[i] > in_sizes[fi]) fi = i;
        if (in_sizes[i] < in_sizes[li]) li = i;
    }
    int wi = 0;
    for (int i = 0; i < n_in; i++) if (i != fi && i != li) wi = i;

    const float* F = (const float*)d_in[fi];
    const float* W = (const float*)d_in[wi];
    const void*  L = d_in[li];

    cudaFuncSetAttribute(gemm_mma_kernel,
                         cudaFuncAttributeMaxDynamicSharedMemorySize, SMEM_TOTAL);

    prep_w_kernel<<<dim3(Cdim, 8), 256>>>(W);
    gemm_mma_kernel<<<148, 512, SMEM_TOTAL>>>(F);
    epilogue_kernel<<<Bdim / 8, 256>>>(L, (float*)d_out, out_size);
}